// round 4
// baseline (speedup 1.0000x reference)
#include <cuda_runtime.h>

constexpr int D  = 128;   // D_IN
constexpr int C  = 64;    // NUM_CLASSES
constexpr int E  = 64;    // D_OUT
constexpr int G1 = 148;   // one block per SM, single resident wave
constexpr int TPB = 384;  // 12 warps
constexpr int GROUPS = 6; // 2 warps per group, one 32KB replica each
constexpr int U  = 8;     // rows per group per iteration (double-buffered)
constexpr int ROWS_ITER = GROUPS * U;  // 48 rows / block / iter

// Zero-initialized scratch; each launch self-cleans it for the next replay.
__device__ float    g_sumS[C * D];
__device__ int      g_cnt[C];
__device__ unsigned g_count   = 0;  // barrier arrivals (reset each launch)
__device__ unsigned g_release = 0;  // monotonically increasing epoch

__global__ __launch_bounds__(TPB, 1)
void fused_kernel(const float* __restrict__ x,
                  const int*   __restrict__ labels,
                  const float* __restrict__ W,
                  const float* __restrict__ bias,
                  float*       __restrict__ out,
                  int n) {
    extern __shared__ float sm[];
    float* acc_all = sm;                              // GROUPS*C*D floats
    int*   scnt    = (int*)(sm + GROUPS * C * D);     // GROUPS*C ints
    __shared__ unsigned rel0;

    const int tid  = threadIdx.x;
    const int grp  = tid >> 6;       // 0..5 (2 warps per group)
    const int ltid = tid & 63;
    const int col2 = ltid * 2;       // owned column pair
    float* acc = acc_all + grp * (C * D);

    if (tid == 0) rel0 = *(volatile unsigned*)&g_release;

    for (int i = tid; i < GROUPS * C * D; i += TPB) acc_all[i] = 0.f;
    for (int i = tid; i < GROUPS * C; i += TPB) scnt[i] = 0;
    __syncthreads();

    const int g = gridDim.x;
    const int chunk = ((n + g * ROWS_ITER - 1) / (g * ROWS_ITER)) * ROWS_ITER;
    const int r0 = blockIdx.x * chunk;
    const int r1 = min(n, r0 + chunk);
    const int span = max(0, r1 - r0);
    const int nfull = span / ROWS_ITER;

    float2 v[2][U];
    int    lab[2][U];

#define LOAD(b, baserow) do {                                            \
        const int _base = (baserow) + grp * U;                           \
        const int4* _lp = (const int4*)(labels + _base);                 \
        int4 _l0 = _lp[0]; int4 _l1 = _lp[1];                            \
        lab[b][0]=_l0.x; lab[b][1]=_l0.y; lab[b][2]=_l0.z; lab[b][3]=_l0.w; \
        lab[b][4]=_l1.x; lab[b][5]=_l1.y; lab[b][6]=_l1.z; lab[b][7]=_l1.w; \
        _Pragma("unroll")                                                \
        for (int _u = 0; _u < U; _u++)                                   \
            v[b][_u] = *(const float2*)(x + (size_t)(_base + _u) * D + col2); \
    } while (0)

#define ACCUM(b) do {                                                    \
        _Pragma("unroll")                                                \
        for (int _u = 0; _u < U; _u++) {                                 \
            float2* _a = (float2*)&acc[lab[b][_u] * D + col2];           \
            float2 _c = *_a;                                             \
            _c.x += v[b][_u].x; _c.y += v[b][_u].y;                      \
            *_a = _c;                                                    \
        }                                                                \
        if (ltid == 0) {                                                 \
            _Pragma("unroll")                                            \
            for (int _u = 0; _u < U; _u++)                               \
                scnt[grp * C + lab[b][_u]] += 1;                         \
        }                                                                \
    } while (0)

    if (nfull > 0) {
        LOAD(0, r0);
        int buf = 0;
        for (int it = 0; it < nfull; it++) {
            const int nextrow = r0 + (it + 1) * ROWS_ITER;
            if (it + 1 < nfull) {
                if (buf) LOAD(0, nextrow); else LOAD(1, nextrow);
            }
            if (buf) ACCUM(1); else ACCUM(0);
            buf ^= 1;
        }
    }

    // tail rows (group 0 only)
    if (grp == 0) {
        for (int m = r0 + nfull * ROWS_ITER; m < r1; m++) {
            int lb = labels[m];
            float2* a = (float2*)&acc[lb * D + col2];
            float2 cu = *a;
            cu.x += x[(size_t)m * D + col2];
            cu.y += x[(size_t)m * D + col2 + 1];
            *a = cu;
            if (ltid == 0) scnt[lb] += 1;
        }
    }
    __syncthreads();

    // merge replicas -> single global accumulator via REDG (no return)
    for (int i = tid; i < C * D; i += TPB) {
        float s = 0.f;
        #pragma unroll
        for (int gg = 0; gg < GROUPS; gg++) s += acc_all[gg * C * D + i];
        atomicAdd(&g_sumS[i], s);
    }
    if (tid < C) {
        int s = 0;
        #pragma unroll
        for (int gg = 0; gg < GROUPS; gg++) s += scnt[gg * C + tid];
        atomicAdd(&g_cnt[tid], s);
    }

    // ---- replay-safe software grid barrier (all blocks co-resident) ----
    __threadfence();
    __syncthreads();
    if (tid == 0) {
        unsigned arrived = atomicAdd(&g_count, 1) + 1;
        if (arrived == (unsigned)gridDim.x) {
            g_count = 0;                 // reset BEFORE release; epoch flag
            __threadfence();             // orders reset + all data before release
            atomicAdd(&g_release, 1u);
        }
        while (*(volatile unsigned*)&g_release == rel0) __nanosleep(32);
    }
    __syncthreads();
    __threadfence();  // order subsequent loads after observing release

    // ---- epilogue: per-class GEMM + divide, then self-clean scratch ----
    for (int c = blockIdx.x; c < C; c += gridDim.x) {
        __shared__ float Srow[D];
        __shared__ float cntf;
        if (tid < D) Srow[tid] = __ldcg(&g_sumS[c * D + tid]);  // bypass L1
        if (tid == 0) cntf = (float)__ldcg(&g_cnt[c]);
        __syncthreads();

        if (tid < E) {
            float a = 0.f;
            #pragma unroll
            for (int dd = 0; dd < D; dd++)
                a += Srow[dd] * __ldg(&W[dd * E + tid]);
            float ct = cntf;
            out[c * E + tid] = (a + ct * bias[tid]) / fmaxf(ct, 1.f);
        }
        __syncthreads();
        // clean for next graph replay (each class owned by exactly one block)
        if (tid < D) g_sumS[c * D + tid] = 0.f;
        if (tid == 0) g_cnt[c] = 0;
        __syncthreads();
    }
#undef LOAD
#undef ACCUM
}

extern "C" void kernel_launch(void* const* d_in, const int* in_sizes, int n_in,
                              void* d_out, int out_size) {
    const float* x      = (const float*)d_in[0];   // [N, 128] f32
    const int*   labels = (const int*)d_in[1];     // [N] i32
    const float* W      = (const float*)d_in[2];   // [128, 64] f32
    const float* bias   = (const float*)d_in[3];   // [64] f32
    float* out = (float*)d_out;                    // [64, 64] f32

    const int n = in_sizes[1];

    const size_t smem1 = (size_t)GROUPS * C * D * sizeof(float)
                       + GROUPS * C * sizeof(int);  // 198,144 B
    cudaFuncSetAttribute(fused_kernel,
                         cudaFuncAttributeMaxDynamicSharedMemorySize,
                         (int)smem1);

    // Residency safety for the software grid barrier: never launch more
    // blocks than can be simultaneously resident.
    int dev = 0, numSM = 148, maxPerSM = 1;
    cudaGetDevice(&dev);
    cudaDeviceGetAttribute(&numSM, cudaDevAttrMultiProcessorCount, dev);
    cudaOccupancyMaxActiveBlocksPerMultiprocessor(&maxPerSM, fused_kernel,
                                                  TPB, smem1);
    int grid = numSM * (maxPerSM > 0 ? maxPerSM : 1);
    if (grid > G1) grid = G1;

    fused_kernel<<<grid, TPB, smem1>>>(x, labels, W, bias, out, n);
}

// round 5
// speedup vs baseline: 1.2627x; 1.2627x over previous
#include <cuda_runtime.h>

constexpr int D  = 128;   // D_IN
constexpr int C  = 64;    // NUM_CLASSES
constexpr int E  = 64;    // D_OUT
constexpr int G1 = 148;
constexpr int TPB = 384;  // 12 warps
constexpr int GROUPS = 6; // 2 warps per group, one 32KB replica each
constexpr int U  = 8;     // rows per group per iteration
constexpr int ROWS_ITER = GROUPS * U;  // 48 rows / block / iter

// Zero-initialized scratch; launch self-cleans for graph replays.
__device__ float    g_sumS[C * D];
__device__ int      g_cnt[C];
__device__ unsigned g_count   = 0;
__device__ unsigned g_release = 0;

__global__ __launch_bounds__(TPB, 1)
void fused_kernel(const float* __restrict__ x,
                  const int*   __restrict__ labels,
                  const float* __restrict__ W,
                  const float* __restrict__ bias,
                  float*       __restrict__ out,
                  int n) {
    extern __shared__ float sm[];
    float* acc_all = sm;                       // GROUPS*C*D floats (192 KB)
    __shared__ int      shist[C];
    __shared__ unsigned rel0;

    const int tid  = threadIdx.x;
    const int grp  = tid >> 6;                 // 0..5
    const int col2 = (tid & 63) * 2;           // owned column pair
    float* acc = acc_all + grp * (C * D);

    if (tid == 0) rel0 = *(volatile unsigned*)&g_release;
    for (int i = tid; i < GROUPS * C * D; i += TPB) acc_all[i] = 0.f;
    if (tid < C) shist[tid] = 0;
    __syncthreads();

    const int g = gridDim.x;
    const int chunk = ((n + g * ROWS_ITER - 1) / (g * ROWS_ITER)) * ROWS_ITER;
    const int r0 = blockIdx.x * chunk;
    const int r1 = min(n, r0 + chunk);
    const int nfull = max(0, r1 - r0) / ROWS_ITER;

    for (int it = 0; it < nfull; it++) {
        const int base = r0 + it * ROWS_ITER + grp * U;

        int lab[U];
        {
            const int4* lp = (const int4*)(labels + base);
            int4 a = lp[0], b = lp[1];
            lab[0]=a.x; lab[1]=a.y; lab[2]=a.z; lab[3]=a.w;
            lab[4]=b.x; lab[5]=b.y; lab[6]=b.z; lab[7]=b.w;
        }

        float2 v[U];
        #pragma unroll
        for (int u = 0; u < U; u++)
            v[u] = *(const float2*)(x + (size_t)(base + u) * D + col2);

        // dup bitmask: dup[u] = label seen earlier in this batch
        unsigned long long seen = 0; unsigned dupm = 0;
        #pragma unroll
        for (int u = 0; u < U; u++) {
            unsigned long long b = 1ull << lab[u];
            dupm |= (seen & b) ? (1u << u) : 0u;
            seen |= b;
        }

        int ad[U];
        #pragma unroll
        for (int u = 0; u < U; u++) ad[u] = lab[u] * D + col2;

        // batched phase: ALL loads first (latencies overlap; first
        // occurrences have pairwise-distinct addresses), then add+store
        float2 cur[U];
        #pragma unroll
        for (int u = 0; u < U; u++)
            cur[u] = *(const float2*)&acc[ad[u]];
        #pragma unroll
        for (int u = 0; u < U; u++) {
            if (!((dupm >> u) & 1u)) {
                cur[u].x += v[u].x; cur[u].y += v[u].y;
                *(float2*)&acc[ad[u]] = cur[u];
            }
        }
        // rare dup rows: serial RMW (program order puts this after the STS)
        if (dupm) {
            #pragma unroll
            for (int u = 0; u < U; u++) {
                if ((dupm >> u) & 1u) {
                    float2 t = *(const float2*)&acc[ad[u]];
                    t.x += v[u].x; t.y += v[u].y;
                    *(float2*)&acc[ad[u]] = t;
                }
            }
        }
    }

    // tail rows (group 0 only)
    if (grp == 0) {
        for (int m = r0 + nfull * ROWS_ITER; m < r1; m++) {
            int lb = labels[m];
            float2* a = (float2*)&acc[lb * D + col2];
            float2 c = *a;
            c.x += x[(size_t)m * D + col2];
            c.y += x[(size_t)m * D + col2 + 1];
            *a = c;
        }
    }

    // counts: separate histogram pass over this block's labels (~4MB total)
    for (int m = r0 + tid; m < r1; m += TPB)
        atomicAdd_block(&shist[labels[m]], 1);
    __syncthreads();

    // merge replicas -> global accumulator (REDG, no return)
    for (int i = tid; i < C * D; i += TPB) {
        float s = 0.f;
        #pragma unroll
        for (int gg = 0; gg < GROUPS; gg++) s += acc_all[gg * C * D + i];
        atomicAdd(&g_sumS[i], s);
    }
    if (tid < C && shist[tid]) atomicAdd(&g_cnt[tid], shist[tid]);

    // ---- replay-safe software grid barrier ----
    __threadfence();
    __syncthreads();
    if (tid == 0) {
        unsigned arrived = atomicAdd(&g_count, 1) + 1;
        if (arrived == (unsigned)gridDim.x) {
            g_count = 0;
            __threadfence();
            atomicAdd(&g_release, 1u);
        }
        while (*(volatile unsigned*)&g_release == rel0) __nanosleep(32);
    }
    __syncthreads();
    __threadfence();

    // ---- epilogue: per-class GEMM + divide, then self-clean ----
    for (int c = blockIdx.x; c < C; c += gridDim.x) {
        __shared__ float Srow[D];
        __shared__ float cntf;
        if (tid < D) Srow[tid] = __ldcg(&g_sumS[c * D + tid]);
        if (tid == 0) cntf = (float)__ldcg(&g_cnt[c]);
        __syncthreads();

        if (tid < E) {
            float a = 0.f;
            #pragma unroll
            for (int dd = 0; dd < D; dd++)
                a += Srow[dd] * __ldg(&W[dd * E + tid]);
            float ct = cntf;
            out[c * E + tid] = (a + ct * bias[tid]) / fmaxf(ct, 1.f);
        }
        __syncthreads();
        if (tid < D) g_sumS[c * D + tid] = 0.f;
        if (tid == 0) g_cnt[c] = 0;
        __syncthreads();
    }
}

extern "C" void kernel_launch(void* const* d_in, const int* in_sizes, int n_in,
                              void* d_out, int out_size) {
    const float* x      = (const float*)d_in[0];   // [N, 128] f32
    const int*   labels = (const int*)d_in[1];     // [N] i32
    const float* W      = (const float*)d_in[2];   // [128, 64] f32
    const float* bias   = (const float*)d_in[3];   // [64] f32
    float* out = (float*)d_out;                    // [64, 64] f32

    const int n = in_sizes[1];

    const size_t smem1 = (size_t)GROUPS * C * D * sizeof(float); // 196,608 B
    cudaFuncSetAttribute(fused_kernel,
                         cudaFuncAttributeMaxDynamicSharedMemorySize,
                         (int)smem1);

    // Residency safety for the software grid barrier
    int dev = 0, numSM = 148, maxPerSM = 1;
    cudaGetDevice(&dev);
    cudaDeviceGetAttribute(&numSM, cudaDevAttrMultiProcessorCount, dev);
    cudaOccupancyMaxActiveBlocksPerMultiprocessor(&maxPerSM, fused_kernel,
                                                  TPB, smem1);
    int grid = numSM * (maxPerSM > 0 ? maxPerSM : 1);
    if (grid > G1) grid = G1;

    fused_kernel<<<grid, TPB, smem1>>>(x, labels, W, bias, out, n);
}